// round 10
// baseline (speedup 1.0000x reference)
#include <cuda_runtime.h>
#include <math.h>

#define Bb 64
#define Ll 128
#define Hh 128
#define Dd 16
#define NTOT (Bb*Ll*Ll)        // 1048576

typedef unsigned long long u64;

// ---------------- scratch ----------------
__device__ float g_Wt[Hh*Dd*Hh];            // [k][d*128+n]   1 MB
__device__ float g_Wrt[Dd*Hh];              // [d*128+n]
__device__ float g_encT[Bb*Hh*Ll];          // [b][k][j]      4 MB
__device__ float g_Q[(size_t)Bb*Dd*Hh*Ll];  // [b][d][n][j]   64 MB
__device__ float g_c[Bb*Ll*Dd];             // [b][j][d]
__device__ float g_LP[2u*NTOT];             // [dh][b][j][m]  8 MB

// ---------------- packed f32x2 helpers ----------------
__device__ __forceinline__ u64 ffma2(u64 a, u64 b, u64 c) {
    u64 d; asm("fma.rn.f32x2 %0, %1, %2, %3;" : "=l"(d) : "l"(a), "l"(b), "l"(c));
    return d;
}
__device__ __forceinline__ u64 dup2(float v) {
    u64 d; asm("mov.b64 %0, {%1, %2};" : "=l"(d) : "f"(v), "f"(v));
    return d;
}
__device__ __forceinline__ float2 unpack2(u64 v) {
    float2 r; asm("mov.b64 {%0, %1}, %2;" : "=f"(r.x), "=f"(r.y) : "l"(v));
    return r;
}

// ---------------- cp.async helpers ----------------
__device__ __forceinline__ unsigned int s2u(const void* p) {
    return (unsigned int)__cvta_generic_to_shared(p);
}
__device__ __forceinline__ void cpa16(unsigned int s, const void* g) {
    asm volatile("cp.async.cg.shared.global [%0], [%1], 16;" :: "r"(s), "l"(g));
}
__device__ __forceinline__ void cpa_commit() {
    asm volatile("cp.async.commit_group;" ::: "memory");
}
template<int N> __device__ __forceinline__ void cpa_wait() {
    asm volatile("cp.async.wait_group %0;" :: "n"(N) : "memory");
}

// ---------------- JAX threefry2x32, partitionable, key=(0,1) --------------
__device__ __forceinline__ unsigned int rotl32(unsigned int v, int s) {
    return (v << s) | (v >> (32 - s));
}
__device__ __forceinline__ unsigned int threefry_bits(unsigned int i) {
    const unsigned int ks0 = 0u, ks1 = 1u, ks2 = 0x1BD11BDAu ^ 0u ^ 1u;
    unsigned int x0 = 0u + ks0;
    unsigned int x1 = i + ks1;
#define TFR(r) { x0 += x1; x1 = rotl32(x1, r) ^ x0; }
    TFR(13) TFR(15) TFR(26) TFR(6)   x0 += ks1; x1 += ks2 + 1u;
    TFR(17) TFR(29) TFR(16) TFR(24)  x0 += ks2; x1 += ks0 + 2u;
    TFR(13) TFR(15) TFR(26) TFR(6)   x0 += ks0; x1 += ks1 + 3u;
    TFR(17) TFR(29) TFR(16) TFR(24)  x0 += ks1; x1 += ks2 + 4u;
    TFR(13) TFR(15) TFR(26) TFR(6)   x0 += ks2; x1 += ks0 + 5u;
#undef TFR
    return x0 ^ x1;
}

__device__ __forceinline__ float tanh_fast(float x) {
    float e = __expf(2.0f * x);
    return 1.0f - __fdividef(2.0f, e + 1.0f);
}

// ---------------- kernel T ----------------
__global__ void k_transpose(const float* __restrict__ W, const float* __restrict__ Wr) {
    int idx = blockIdx.x * blockDim.x + threadIdx.x;
    if (idx < Hh * Hh * Dd) {
        int k = idx >> 11;
        int rem = idx & 2047;
        int d = rem >> 7;
        int n = rem & 127;
        g_Wt[idx] = W[(k * Hh + n) * Dd + d];
    }
    if (idx < Dd * Hh) {
        int d = idx >> 7, n = idx & 127;
        g_Wrt[idx] = Wr[n * Dd + d];
    }
}

// ---------------- kernel ET ----------------
__global__ void k_encT(const float* __restrict__ enc) {
    __shared__ float t[32][33];
    int b = blockIdx.z;
    int j0 = blockIdx.x * 32, k0 = blockIdx.y * 32;
    int tx = threadIdx.x, ty = threadIdx.y;
#pragma unroll
    for (int i = 0; i < 32; i += 8)
        t[ty + i][tx] = enc[b * 16384 + (j0 + ty + i) * 128 + k0 + tx];
    __syncthreads();
#pragma unroll
    for (int i = 0; i < 32; i += 8)
        g_encT[b * 16384 + (k0 + ty + i) * 128 + j0 + tx] = t[tx][ty + i];
}

// ---------------- kernel C ----------------
__global__ void k_linear(const float* __restrict__ enc, const float* __restrict__ Wl,
                         const float* __restrict__ Bvec) {
    int idx = blockIdx.x * blockDim.x + threadIdx.x;
    if (idx >= Bb * Ll * Dd) return;
    int d = idx & 15;
    int bj = idx >> 4;
    const float* e = enc + (size_t)bj * Hh;
    float acc = Bvec[d];
#pragma unroll 8
    for (int k = 0; k < Hh; k++) acc = fmaf(e[k], Wl[k * Dd + d], acc);
    g_c[idx] = acc;
}

#define ROWOP8(r, aval) { u64 a_ = dup2(aval); \
    acc[r][0] = ffma2(a_, b01.x, acc[r][0]); \
    acc[r][1] = ffma2(a_, b01.y, acc[r][1]); \
    acc[r][2] = ffma2(a_, b23.x, acc[r][2]); \
    acc[r][3] = ffma2(a_, b23.y, acc[r][3]); }

#define ROWOP2(r, aval) { u64 a_ = dup2(aval); \
    acc[r][0] = ffma2(a_, b01.x, acc[r][0]); \
    acc[r][1] = ffma2(a_, b01.y, acc[r][1]); }

// ---------------- kernel 1: Q[b][d][n][j] = (enc_b @ Wt_d)^T + Wrt --------
// grid (16 d, 16 g) = 256 CTAs, one wave. Each CTA: sB (Wt_d) resident,
// loops 4 b-tiles = 16 streamed sA chunks (32 k x 128 j), per-warp-partitioned
// double-buffered cp.async (no block barriers in mainloop).
extern __shared__ char smemG[];
__global__ __launch_bounds__(256, 2) void k_gemm1() {
    float* sB  = (float*)smemG;                    // [128 k][128 n] 64 KB
    float* sA0 = (float*)(smemG + 65536);          // [32 k][128 j] 16 KB
    float* sA1 = (float*)(smemG + 65536 + 16384);  // [32 k][128 j] 16 KB
    int d = blockIdx.x, g0 = blockIdx.y;
    int tid = threadIdx.x;
    int tx = tid & 15, ty = tid >> 4;
    int w = tid >> 5, l = tid & 31;                // warp, lane

    const float4* wsrc = (const float4*)g_Wt;

    // warp-partitioned chunk refill: warp w copies j-columns [w*16, w*16+16)
    // chunk c: b = g0 + 16*(c>>2), k-rows (c&3)*32 .. +31
    auto refill = [&](float* buf, int c) {
        int b = g0 + 16 * (c >> 2);
        int kc = c & 3;
        const float4* src = (const float4*)(g_encT + (size_t)b * 16384) + kc * 1024;
        unsigned int dst = s2u(buf);
#pragma unroll
        for (int t = 0; t < 4; t++) {
            int kk = t * 8 + (l >> 2);
            int gg = w * 4 + (l & 3);
            cpa16(dst + (unsigned)(kk * 32 + gg) * 16, src + kk * 32 + gg);
        }
    };

    // prologue: group0 = sB + chunk0(own cols); group1 = chunk1(own cols)
    {
        unsigned int sBa = s2u(sB);
        for (int idx = tid; idx < 4096; idx += 256) {
            int k = idx >> 5, gg = idx & 31;
            cpa16(sBa + (unsigned)(k * 32 + gg) * 16, wsrc + (size_t)k * 512 + d * 32 + gg);
        }
        refill(sA0, 0);
        cpa_commit();
        refill(sA1, 1);
        cpa_commit();
    }
    cpa_wait<1>();
    __syncthreads();   // sB (cross-warp) + chunk0 visible

    // Wrt hoisted to registers (d fixed for whole CTA)
    float wr[8];
#pragma unroll
    for (int c = 0; c < 8; c++) {
        int col = (c < 4) ? (tx * 4 + c) : (64 + tx * 4 + (c - 4));
        wr[c] = g_Wrt[d * 128 + col];
    }

    u64 acc[8][4];
#pragma unroll
    for (int r = 0; r < 8; r++)
#pragma unroll
        for (int q = 0; q < 4; q++) acc[r][q] = 0ull;

    for (int c = 0; c < 16; c++) {
        float* sAc = (c & 1) ? sA1 : sA0;
        int k0 = (c & 3) * 32;
        float4 a01_nx = *(const float4*)&sAc[ty * 8];
        float4 a23_nx = *(const float4*)&sAc[ty * 8 + 4];
        ulonglong2 b01_nx = *(const ulonglong2*)&sB[k0 * 128 + tx * 4];
        ulonglong2 b23_nx = *(const ulonglong2*)&sB[k0 * 128 + 64 + tx * 4];
#pragma unroll 4
        for (int kk = 0; kk < 32; kk++) {
            float4 a01 = a01_nx, a23 = a23_nx;
            ulonglong2 b01 = b01_nx, b23 = b23_nx;
            int kn = kk + 1;   // kk=31: stray reads into adjacent allocated smem
            a01_nx = *(const float4*)&sAc[kn * 128 + ty * 8];
            a23_nx = *(const float4*)&sAc[kn * 128 + ty * 8 + 4];
            b01_nx = *(const ulonglong2*)&sB[(k0 + kn) * 128 + tx * 4];
            b23_nx = *(const ulonglong2*)&sB[(k0 + kn) * 128 + 64 + tx * 4];
            ROWOP8(0, a01.x) ROWOP8(1, a01.y) ROWOP8(2, a01.z) ROWOP8(3, a01.w)
            ROWOP8(4, a23.x) ROWOP8(5, a23.y) ROWOP8(6, a23.z) ROWOP8(7, a23.w)
        }
        // refill just-read buffer with chunk c+2 (own columns only -> no barrier)
        if (c <= 13) {
            refill(sAc, c + 2);
            cpa_commit();
            cpa_wait<1>();
        } else {
            cpa_wait<0>();
        }
        __syncwarp();

        if ((c & 3) == 3) {
            // epilogue for this b-tile
            int b = g0 + 16 * (c >> 2);
#pragma unroll
            for (int q = 0; q < 4; q++) {
                int colbase = (q < 2) ? (tx * 4 + 2 * q) : (64 + tx * 4 + 2 * (q - 2));
#pragma unroll
                for (int h = 0; h < 2; h++) {
                    int col = colbase + h;
                    int ci = (q < 2) ? (2 * q + h) : (4 + 2 * (q - 2) + h);
                    float v[8];
#pragma unroll
                    for (int r = 0; r < 8; r++) {
                        float2 s = unpack2(acc[r][q]);
                        v[r] = (h == 0 ? s.x : s.y) + wr[ci];
                    }
                    float* dst = g_Q + ((size_t)(b * 16 + d) * 128 + col) * 128 + ty * 8;
                    *(float4*)dst       = make_float4(v[0], v[1], v[2], v[3]);
                    *(float4*)(dst + 4) = make_float4(v[4], v[5], v[6], v[7]);
                }
            }
#pragma unroll
            for (int r = 0; r < 8; r++)
#pragma unroll
                for (int q = 0; q < 4; q++) acc[r][q] = 0ull;
        }
    }
}

// ---------------- kernel 2: bilinear + tanh + partial logits --------------
// grid (2 mh, 2 dh, 64 b) = 256 CTAs, one wave. 16 phases (8 d x 2 n-halves),
// per-warp-partitioned double-buffered sQ (no block barriers in mainloop).
extern __shared__ char smemF[];
__global__ __launch_bounds__(256, 2) void k_final(const float* __restrict__ U) {
    float* sQ0 = (float*)smemF;                    // [64 n][128 j] 32 KB
    float* sQ1 = (float*)(smemF + 32768);          // [64 n][128 j] 32 KB
    float* sE  = (float*)(smemF + 65536);          // [128 n][64 m] 32 KB
    float* sC  = (float*)(smemF + 98304);          // [128 j][16 d] 8 KB
    float* sU  = sC + 2048;
    int mh = blockIdx.x, dh = blockIdx.y, b = blockIdx.z;
    int tid = threadIdx.x;
    int tx = tid & 15, ty = tid >> 4;
    int w = tid >> 5, l = tid & 31;

    const float4* qsrc = (const float4*)g_Q;

    // warp-partitioned refill of a 64-n half of Q_d: warp w copies j-cols [w*16,+16)
    auto refillQ = [&](float* buf, int p) {
        int d = dh * 8 + (p >> 1), hh = p & 1;
        const float4* src = qsrc + (size_t)(b * 16 + d) * 4096 + hh * 2048;
        unsigned int dst = s2u(buf);
#pragma unroll
        for (int t = 0; t < 8; t++) {
            int nn = t * 8 + (l >> 2);
            int gg = w * 4 + (l & 3);
            cpa16(dst + (unsigned)(nn * 32 + gg) * 16, src + nn * 32 + gg);
        }
    };

    // prologue: group0 = sE + phase0(own); group1 = phase1(own); sync loads sC/sU
    {
        const float4* esrc = (const float4*)(g_encT + (size_t)b * 16384);
        unsigned int ea = s2u(sE);
        for (int idx = tid; idx < 2048; idx += 256) {
            int n = idx >> 4, gg = idx & 15;
            cpa16(ea + (unsigned)idx * 16, esrc + n * 32 + mh * 16 + gg);
        }
        refillQ(sQ0, 0);
        cpa_commit();
        refillQ(sQ1, 1);
        cpa_commit();
        const float4* csrc = (const float4*)(g_c + b * 2048);
        float4* cdst = (float4*)sC;
        for (int idx = tid; idx < 512; idx += 256) cdst[idx] = csrc[idx];
        if (tid < 16) sU[tid] = U[tid];
    }
    cpa_wait<1>();
    __syncthreads();   // sE/sC (cross-warp) + phase0 visible

    float logit[8][4];
#pragma unroll
    for (int r = 0; r < 8; r++)
#pragma unroll
        for (int q = 0; q < 4; q++) logit[r][q] = 0.0f;

    u64 acc[8][2];

    for (int p = 0; p < 16; p++) {
        int dloc = p >> 1, hh = p & 1;
        int d = dh * 8 + dloc;
        float* sQc = hh ? sQ1 : sQ0;
        if (hh == 0) {
#pragma unroll
            for (int r = 0; r < 8; r++) { acc[r][0] = 0ull; acc[r][1] = 0ull; }
        }
        {
            float4 a01_nx = *(const float4*)&sQc[ty * 8];
            float4 a23_nx = *(const float4*)&sQc[ty * 8 + 4];
            ulonglong2 b01_nx = *(const ulonglong2*)&sE[(hh * 64) * 64 + tx * 4];
#pragma unroll 4
            for (int nn = 0; nn < 64; nn++) {
                float4 a01 = a01_nx, a23 = a23_nx;
                ulonglong2 b01 = b01_nx;
                int kn = nn + 1;   // nn=63: stray reads into adjacent allocated smem
                a01_nx = *(const float4*)&sQc[kn * 128 + ty * 8];
                a23_nx = *(const float4*)&sQc[kn * 128 + ty * 8 + 4];
                b01_nx = *(const ulonglong2*)&sE[(hh * 64 + kn) * 64 + tx * 4];
                ROWOP2(0, a01.x) ROWOP2(1, a01.y) ROWOP2(2, a01.z) ROWOP2(3, a01.w)
                ROWOP2(4, a23.x) ROWOP2(5, a23.y) ROWOP2(6, a23.z) ROWOP2(7, a23.w)
            }
        }
        if (hh == 1) {
            float ud = sU[d];
#pragma unroll
            for (int r = 0; r < 8; r++) {
                float cr = sC[(ty * 8 + r) * 16 + d];
                float2 s0 = unpack2(acc[r][0]);
                float2 s1 = unpack2(acc[r][1]);
                logit[r][0] = fmaf(ud, tanh_fast(s0.x + cr), logit[r][0]);
                logit[r][1] = fmaf(ud, tanh_fast(s0.y + cr), logit[r][1]);
                logit[r][2] = fmaf(ud, tanh_fast(s1.x + cr), logit[r][2]);
                logit[r][3] = fmaf(ud, tanh_fast(s1.y + cr), logit[r][3]);
            }
        }
        if (p <= 13) {
            refillQ(sQc, p + 2);
            cpa_commit();
            cpa_wait<1>();
        } else {
            cpa_wait<0>();
        }
        __syncwarp();
    }

    // write partial logits
#pragma unroll
    for (int r = 0; r < 8; r++) {
        int j = ty * 8 + r;
        size_t o = (size_t)dh * NTOT + (size_t)b * 16384 + (size_t)j * 128 + mh * 64 + tx * 4;
        *(float4*)(g_LP + o) = make_float4(logit[r][0], logit[r][1], logit[r][2], logit[r][3]);
    }
}

// ---------------- kernel E: combine + mask/sigmoid/RNG/entropy ------------
__global__ __launch_bounds__(256) void k_epi(const float* __restrict__ lb,
                                             float* __restrict__ out) {
    int gid = blockIdx.x * blockDim.x + threadIdx.x;
    const float4* P0 = (const float4*)g_LP;
    const float4* P1 = P0 + (NTOT / 4);
    float4 a = P0[gid], c = P1[gid];
    float lbias = lb[0];
    float s4[4] = { a.x + c.x + lbias, a.y + c.y + lbias,
                    a.z + c.z + lbias, a.w + c.w + lbias };
    int flat0 = gid * 4;
    int j = (flat0 >> 7) & 127;
    int m0 = flat0 & 127;
    float vs[4], ve[4];
#pragma unroll
    for (int e = 0; e < 4; e++) {
        float s = s4[e];
        if (j == m0 + e) s -= 1e8f;
        s4[e] = s;
        float p = 1.0f / (1.0f + expf(-s));
        unsigned int bits = threefry_bits((unsigned int)(flat0 + e));
        float u = __uint_as_float((bits >> 9) | 0x3f800000u) - 1.0f;
        vs[e] = (u < p) ? 1.0f : 0.0f;
        float ax = fabsf(s);
        float lse = log1pf(expf(-ax));
        float spp = fmaxf(s, 0.0f) + lse;
        float spn = fmaxf(-s, 0.0f) + lse;
        ve[e] = p * spn + (1.0f - p) * spp;
    }
    ((float4*)out)[gid]                = make_float4(vs[0], vs[1], vs[2], vs[3]);
    ((float4*)(out + NTOT))[gid]       = make_float4(s4[0], s4[1], s4[2], s4[3]);
    ((float4*)(out + 2u * NTOT))[gid]  = make_float4(ve[0], ve[1], ve[2], ve[3]);
}

// ---------------- launch ----------------
extern "C" void kernel_launch(void* const* d_in, const int* in_sizes, int n_in,
                              void* d_out, int out_size) {
    const float* enc  = (const float*)d_in[0];
    const float* W    = (const float*)d_in[1];
    const float* Wl   = (const float*)d_in[2];
    const float* Wr   = (const float*)d_in[3];
    const float* U    = (const float*)d_in[4];
    const float* Bv   = (const float*)d_in[5];
    const float* lbias= (const float*)d_in[6];
    float* out = (float*)d_out;

    k_transpose<<<(Hh * Hh * Dd + 255) / 256, 256>>>(W, Wr);
    k_encT<<<dim3(4, 4, Bb), dim3(32, 8)>>>(enc);
    k_linear<<<(Bb * Ll * Dd + 255) / 256, 256>>>(enc, Wl, Bv);

    int smemG_bytes = 65536 + 16384 * 2 + 1024;   // sB + 2 sA bufs + pad
    cudaFuncSetAttribute(k_gemm1, cudaFuncAttributeMaxDynamicSharedMemorySize, smemG_bytes);
    k_gemm1<<<dim3(16, 16), 256, smemG_bytes>>>();

    int smemF_bytes = 32768 * 2 + 32768 + 8192 + 64 + 512;  // 2 sQ + sE + sC + sU + pad
    cudaFuncSetAttribute(k_final, cudaFuncAttributeMaxDynamicSharedMemorySize, smemF_bytes);
    k_final<<<dim3(2, 2, Bb), 256, smemF_bytes>>>(U);

    k_epi<<<NTOT / 4 / 256, 256>>>(lbias, out);
}

// round 13
// speedup vs baseline: 1.0163x; 1.0163x over previous
#include <cuda_runtime.h>
#include <math.h>

#define Bb 64
#define Ll 128
#define Hh 128
#define Dd 16
#define NTOT (Bb*Ll*Ll)        // 1048576

typedef unsigned long long u64;

// ---------------- scratch ----------------
__device__ float g_Wt[Hh*Dd*Hh];            // [k][d*128+n]   1 MB
__device__ float g_Wrt[Dd*Hh];              // [d*128+n]
__device__ float g_encT[Bb*Hh*Ll];          // [b][k][j]      4 MB
__device__ float g_Q[(size_t)Bb*Dd*Hh*Ll];  // [b][d][n][j]   64 MB
__device__ float g_c[Bb*Ll*Dd];             // [b][j][d]

// ---------------- packed f32x2 helpers ----------------
__device__ __forceinline__ u64 ffma2(u64 a, u64 b, u64 c) {
    u64 d; asm("fma.rn.f32x2 %0, %1, %2, %3;" : "=l"(d) : "l"(a), "l"(b), "l"(c));
    return d;
}
__device__ __forceinline__ u64 dup2(float v) {
    u64 d; asm("mov.b64 %0, {%1, %2};" : "=l"(d) : "f"(v), "f"(v));
    return d;
}
__device__ __forceinline__ float2 unpack2(u64 v) {
    float2 r; asm("mov.b64 {%0, %1}, %2;" : "=f"(r.x), "=f"(r.y) : "l"(v));
    return r;
}

// ---------------- cp.async helpers ----------------
__device__ __forceinline__ unsigned int s2u(const void* p) {
    return (unsigned int)__cvta_generic_to_shared(p);
}
__device__ __forceinline__ void cpa16(unsigned int s, const void* g) {
    asm volatile("cp.async.cg.shared.global [%0], [%1], 16;" :: "r"(s), "l"(g));
}
__device__ __forceinline__ void cpa_commit() {
    asm volatile("cp.async.commit_group;" ::: "memory");
}
template<int N> __device__ __forceinline__ void cpa_wait() {
    asm volatile("cp.async.wait_group %0;" :: "n"(N) : "memory");
}

// ---------------- JAX threefry2x32, partitionable, key=(0,1) --------------
__device__ __forceinline__ unsigned int rotl32(unsigned int v, int s) {
    return (v << s) | (v >> (32 - s));
}
__device__ __forceinline__ unsigned int threefry_bits(unsigned int i) {
    const unsigned int ks0 = 0u, ks1 = 1u, ks2 = 0x1BD11BDAu ^ 0u ^ 1u;
    unsigned int x0 = 0u + ks0;
    unsigned int x1 = i + ks1;
#define TFR(r) { x0 += x1; x1 = rotl32(x1, r) ^ x0; }
    TFR(13) TFR(15) TFR(26) TFR(6)   x0 += ks1; x1 += ks2 + 1u;
    TFR(17) TFR(29) TFR(16) TFR(24)  x0 += ks2; x1 += ks0 + 2u;
    TFR(13) TFR(15) TFR(26) TFR(6)   x0 += ks0; x1 += ks1 + 3u;
    TFR(17) TFR(29) TFR(16) TFR(24)  x0 += ks1; x1 += ks2 + 4u;
    TFR(13) TFR(15) TFR(26) TFR(6)   x0 += ks2; x1 += ks0 + 5u;
#undef TFR
    return x0 ^ x1;
}

__device__ __forceinline__ float tanh_fast(float x) {
    float e = __expf(2.0f * x);
    return 1.0f - __fdividef(2.0f, e + 1.0f);
}

// ---------------- fused prep: transpose W/Wr (1024 blks), encT (1024), linear (512)
__global__ void k_prep(const float* __restrict__ enc, const float* __restrict__ W,
                       const float* __restrict__ Wr, const float* __restrict__ Wl,
                       const float* __restrict__ Bvec) {
    __shared__ float t[32][33];
    int blk = blockIdx.x;
    int tid = threadIdx.x;
    if (blk < 1024) {
        // W[k,n,d] -> Wt[k][d*128+n]; Wr[n,d] -> Wrt[d*128+n]
        int idx = blk * 256 + tid;           // covers 262144 = 128*128*16
        int k = idx >> 11;
        int rem = idx & 2047;
        int d = rem >> 7;
        int n = rem & 127;
        g_Wt[idx] = W[(k * Hh + n) * Dd + d];
        if (idx < Dd * Hh) {
            int dd = idx >> 7, nn = idx & 127;
            g_Wrt[idx] = Wr[nn * Dd + dd];
        }
    } else if (blk < 2048) {
        // enc[b][j][k] -> encT[b][k][j], 32x32 tiles
        int bb = blk - 1024;
        int b = bb >> 4;
        int rem = bb & 15;
        int j0 = (rem & 3) * 32, k0 = (rem >> 2) * 32;
        int tx = tid & 31, ty = tid >> 5;
#pragma unroll
        for (int i = 0; i < 32; i += 8)
            t[ty + i][tx] = enc[b * 16384 + (j0 + ty + i) * 128 + k0 + tx];
        __syncthreads();
#pragma unroll
        for (int i = 0; i < 32; i += 8)
            g_encT[b * 16384 + (k0 + ty + i) * 128 + j0 + tx] = t[tx][ty + i];
    } else {
        // c[b,j,d] = enc[b,j,:].Wl[:,d] + Bvec[d]
        int idx = (blk - 2048) * 256 + tid;  // covers 131072 = 64*128*16
        int d = idx & 15;
        int bj = idx >> 4;
        const float* e = enc + (size_t)bj * Hh;
        float acc = Bvec[d];
#pragma unroll 8
        for (int k = 0; k < Hh; k++) acc = fmaf(e[k], Wl[k * Dd + d], acc);
        g_c[idx] = acc;
    }
}

#define ROWOP8(r, aval) { u64 a_ = dup2(aval); \
    acc[r][0] = ffma2(a_, b01.x, acc[r][0]); \
    acc[r][1] = ffma2(a_, b01.y, acc[r][1]); \
    acc[r][2] = ffma2(a_, b23.x, acc[r][2]); \
    acc[r][3] = ffma2(a_, b23.y, acc[r][3]); }

// ---------------- kernel 1 (R9 proven): Q[b][d][n][j] = (enc_b@Wt_d)^T+Wrt
// grid (16 d, 64 b), block 256, tile 128j x 128n, 8x8/thread,
// cp.async double-buffered sA chunks of 32 k
extern __shared__ char smemG[];
__global__ __launch_bounds__(256, 2) void k_gemm1() {
    float* sB  = (float*)smemG;                    // [128 k][128 n] 64 KB
    float* sA0 = (float*)(smemG + 65536);          // [32 k][128 j] 16 KB
    float* sA1 = (float*)(smemG + 65536 + 16384);  // [32 k][128 j] 16 KB
    int d = blockIdx.x, b = blockIdx.y;
    int tid = threadIdx.x;
    int tx = tid & 15, ty = tid >> 4;

    const float4* wsrc = (const float4*)g_Wt;
    const float4* asrc = (const float4*)(g_encT + (size_t)b * 16384);

    {
        unsigned int sBa = s2u(sB);
        for (int idx = tid; idx < 4096; idx += 256) {
            int k = idx >> 5, g = idx & 31;
            cpa16(sBa + (unsigned)(k * 32 + g) * 16, wsrc + (size_t)k * 512 + d * 32 + g);
        }
        unsigned int a0 = s2u(sA0);
        for (int idx = tid; idx < 1024; idx += 256)
            cpa16(a0 + (unsigned)idx * 16, asrc + idx);
        cpa_commit();
        unsigned int a1 = s2u(sA1);
        for (int idx = tid; idx < 1024; idx += 256)
            cpa16(a1 + (unsigned)idx * 16, asrc + 1024 + idx);
        cpa_commit();
    }
    cpa_wait<1>();
    __syncthreads();

    u64 acc[8][4];
#pragma unroll
    for (int r = 0; r < 8; r++)
#pragma unroll
        for (int q = 0; q < 4; q++) acc[r][q] = 0ull;

    for (int kc = 0; kc < 4; kc++) {
        float* sAc = (kc & 1) ? sA1 : sA0;
        int k0 = kc * 32;
        float4 a01_nx = *(const float4*)&sAc[ty * 8];
        float4 a23_nx = *(const float4*)&sAc[ty * 8 + 4];
        ulonglong2 b01_nx = *(const ulonglong2*)&sB[k0 * 128 + tx * 4];
        ulonglong2 b23_nx = *(const ulonglong2*)&sB[k0 * 128 + 64 + tx * 4];
#pragma unroll 4
        for (int kk = 0; kk < 32; kk++) {
            float4 a01 = a01_nx, a23 = a23_nx;
            ulonglong2 b01 = b01_nx, b23 = b23_nx;
            int kn = kk + 1;   // kk=31: stray reads into adjacent allocated smem
            a01_nx = *(const float4*)&sAc[kn * 128 + ty * 8];
            a23_nx = *(const float4*)&sAc[kn * 128 + ty * 8 + 4];
            b01_nx = *(const ulonglong2*)&sB[(k0 + kn) * 128 + tx * 4];
            b23_nx = *(const ulonglong2*)&sB[(k0 + kn) * 128 + 64 + tx * 4];
            ROWOP8(0, a01.x) ROWOP8(1, a01.y) ROWOP8(2, a01.z) ROWOP8(3, a01.w)
            ROWOP8(4, a23.x) ROWOP8(5, a23.y) ROWOP8(6, a23.z) ROWOP8(7, a23.w)
        }
        __syncthreads();
        if (kc + 2 < 4) {
            unsigned int aa = s2u(sAc);
            for (int idx = tid; idx < 1024; idx += 256)
                cpa16(aa + (unsigned)idx * 16, asrc + (kc + 2) * 1024 + idx);
            cpa_commit();
            cpa_wait<1>();
        } else {
            cpa_wait<0>();
        }
        __syncthreads();
    }

#pragma unroll
    for (int q = 0; q < 4; q++) {
        int colbase = (q < 2) ? (tx * 4 + 2 * q) : (64 + tx * 4 + 2 * (q - 2));
#pragma unroll
        for (int h = 0; h < 2; h++) {
            int col = colbase + h;
            float wr = g_Wrt[d * 128 + col];
            float v[8];
#pragma unroll
            for (int r = 0; r < 8; r++) {
                float2 s = unpack2(acc[r][q]);
                v[r] = (h == 0 ? s.x : s.y) + wr;
            }
            float* dst = g_Q + ((size_t)(b * 16 + d) * 128 + col) * 128 + ty * 8;
            *(float4*)dst       = make_float4(v[0], v[1], v[2], v[3]);
            *(float4*)(dst + 4) = make_float4(v[4], v[5], v[6], v[7]);
        }
    }
}

// ---------------- kernel 2: bilinear + tanh + full epilogue ---------------
// grid (4 mh, 64 b) = 256 CTAs. Tile 128j x 32m, ALL 16 d (32 phases of
// 64-n halves). j-paired FFMA2 (A natural u64 pairs, only m-scalars dup'd).
// Inline mask/sigmoid/threefry/entropy epilogue writes the 3 outputs.
extern __shared__ char smemF[];
__global__ __launch_bounds__(256, 2) void k_final(const float* __restrict__ U,
                                                  const float* __restrict__ lb,
                                                  float* __restrict__ out) {
    float* sQ0 = (float*)smemF;                    // [64 n][128 j] 32 KB
    float* sQ1 = (float*)(smemF + 32768);          // [64 n][128 j] 32 KB
    float* sE  = (float*)(smemF + 65536);          // [128 n][32 m] 16 KB
    float* sC  = (float*)(smemF + 65536 + 16384);  // [128 j][16 d] 8 KB
    float* sU  = sC + 2048;
    int mh = blockIdx.x, b = blockIdx.y;
    int tid = threadIdx.x;
    int tx = tid & 15, ty = tid >> 4;              // m-pair tx*2, j rows ty*8
    int w = tid >> 5, l = tid & 31;

    const float4* qsrc = (const float4*)g_Q;

    // warp-partitioned refill of a 64-n half of Q_d (warp w owns j [w*16,+16))
    auto refillQ = [&](float* buf, int p) {
        int d = p >> 1, hh = p & 1;
        const float4* src = qsrc + (size_t)(b * 16 + d) * 4096 + hh * 2048;
        unsigned int dst = s2u(buf);
#pragma unroll
        for (int t = 0; t < 8; t++) {
            int nn = t * 8 + (l >> 2);
            int gg = w * 4 + (l & 3);
            cpa16(dst + (unsigned)(nn * 32 + gg) * 16, src + nn * 32 + gg);
        }
    };

    // prologue
    {
        const float4* esrc = (const float4*)(g_encT + (size_t)b * 16384);
        unsigned int ea = s2u(sE);
        for (int idx = tid; idx < 1024; idx += 256) {
            int n = idx >> 3, gg = idx & 7;
            cpa16(ea + (unsigned)idx * 16, esrc + n * 32 + mh * 8 + gg);
        }
        refillQ(sQ0, 0);
        cpa_commit();
        refillQ(sQ1, 1);
        cpa_commit();
        const float4* csrc = (const float4*)(g_c + b * 2048);
        float4* cdst = (float4*)sC;
        for (int idx = tid; idx < 512; idx += 256) cdst[idx] = csrc[idx];
        if (tid < 16) sU[tid] = U[tid];
    }
    cpa_wait<1>();
    __syncthreads();   // sE/sC cross-warp + phase0 visible

    float logit[2][8];
#pragma unroll
    for (int mi = 0; mi < 2; mi++)
#pragma unroll
        for (int r = 0; r < 8; r++) logit[mi][r] = 0.0f;

    u64 acc[2][4];     // [mi][j-pair]

    for (int p = 0; p < 32; p++) {
        int d = p >> 1, hh = p & 1;
        float* sQc = hh ? sQ1 : sQ0;
        if (hh == 0) {
#pragma unroll
            for (int mi = 0; mi < 2; mi++)
#pragma unroll
                for (int q = 0; q < 4; q++) acc[mi][q] = 0ull;
        }
        {
            ulonglong2 a01_nx = *(const ulonglong2*)&sQc[ty * 8];
            ulonglong2 a23_nx = *(const ulonglong2*)&sQc[ty * 8 + 4];
            float2 e_nx = *(const float2*)&sE[(hh * 64) * 32 + tx * 2];
#pragma unroll 4
            for (int nn = 0; nn < 64; nn++) {
                ulonglong2 a01 = a01_nx, a23 = a23_nx;
                float2 ee = e_nx;
                int kn = nn + 1;   // nn=63: stray reads into adjacent allocated smem
                a01_nx = *(const ulonglong2*)&sQc[kn * 128 + ty * 8];
                a23_nx = *(const ulonglong2*)&sQc[kn * 128 + ty * 8 + 4];
                e_nx   = *(const float2*)&sE[(hh * 64 + kn) * 32 + tx * 2];
                u64 e0 = dup2(ee.x), e1 = dup2(ee.y);
                acc[0][0] = ffma2(a01.x, e0, acc[0][0]);
                acc[0][1] = ffma2(a01.y, e0, acc[0][1]);
                acc[0][2] = ffma2(a23.x, e0, acc[0][2]);
                acc[0][3] = ffma2(a23.y, e0, acc[0][3]);
                acc[1][0] = ffma2(a01.x, e1, acc[1][0]);
                acc[1][1] = ffma2(a01.y, e1, acc[1][1]);
                acc[1][2] = ffma2(a23.x, e1, acc[1][2]);
                acc[1][3] = ffma2(a23.y, e1, acc[1][3]);
            }
        }
        if (hh == 1) {
            float ud = sU[d];
#pragma unroll
            for (int mi = 0; mi < 2; mi++)
#pragma unroll
                for (int q = 0; q < 4; q++) {
                    float2 s = unpack2(acc[mi][q]);
                    float c0 = sC[(ty * 8 + 2 * q) * 16 + d];
                    float c1 = sC[(ty * 8 + 2 * q + 1) * 16 + d];
                    logit[mi][2 * q]     = fmaf(ud, tanh_fast(s.x + c0), logit[mi][2 * q]);
                    logit[mi][2 * q + 1] = fmaf(ud, tanh_fast(s.y + c1), logit[mi][2 * q + 1]);
                }
        }
        if (p <= 29) {
            refillQ(sQc, p + 2);
            cpa_commit();
            cpa_wait<1>();
        } else {
            cpa_wait<0>();
        }
        __syncwarp();
    }

    // inline epilogue: mask, sigmoid, threefry sample, entropy; 3 outputs
    float lbias = lb[0];
    float* outS = out;
    float* outM = out + NTOT;
    float* outE = out + 2u * NTOT;
    int m0 = mh * 32 + tx * 2;
#pragma unroll
    for (int r = 0; r < 8; r++) {
        int j = ty * 8 + r;
        float vs[2], vm[2], ve[2];
#pragma unroll
        for (int mi = 0; mi < 2; mi++) {
            int m = m0 + mi;
            float s = logit[mi][r] + lbias;
            if (j == m) s -= 1e8f;
            float pr = 1.0f / (1.0f + expf(-s));
            unsigned int bits = threefry_bits((unsigned int)((b * Ll + j) * Ll + m));
            float u = __uint_as_float((bits >> 9) | 0x3f800000u) - 1.0f;
            vs[mi] = (u < pr) ? 1.0f : 0.0f;
            vm[mi] = s;
            float ax = fabsf(s);
            float lse = log1pf(expf(-ax));
            float spp = fmaxf(s, 0.0f) + lse;
            float spn = fmaxf(-s, 0.0f) + lse;
            ve[mi] = pr * spn + (1.0f - pr) * spp;
        }
        size_t o = (size_t)(b * Ll + j) * Ll + m0;
        *(float2*)(outS + o) = make_float2(vs[0], vs[1]);
        *(float2*)(outM + o) = make_float2(vm[0], vm[1]);
        *(float2*)(outE + o) = make_float2(ve[0], ve[1]);
    }
}

// ---------------- launch ----------------
extern "C" void kernel_launch(void* const* d_in, const int* in_sizes, int n_in,
                              void* d_out, int out_size) {
    const float* enc  = (const float*)d_in[0];
    const float* W    = (const float*)d_in[1];
    const float* Wl   = (const float*)d_in[2];
    const float* Wr   = (const float*)d_in[3];
    const float* U    = (const float*)d_in[4];
    const float* Bv   = (const float*)d_in[5];
    const float* lbias= (const float*)d_in[6];
    float* out = (float*)d_out;

    k_prep<<<1024 + 1024 + 512, 256>>>(enc, W, Wr, Wl, Bv);

    int smemG_bytes = 65536 + 16384 * 2 + 1024;
    cudaFuncSetAttribute(k_gemm1, cudaFuncAttributeMaxDynamicSharedMemorySize, smemG_bytes);
    k_gemm1<<<dim3(16, Bb), 256, smemG_bytes>>>();

    int smemF_bytes = 32768 * 2 + 16384 + 8192 + 64 + 512;
    cudaFuncSetAttribute(k_final, cudaFuncAttributeMaxDynamicSharedMemorySize, smemF_bytes);
    k_final<<<dim3(4, Bb), 256, smemF_bytes>>>(U, lbias, out);
}

// round 14
// speedup vs baseline: 1.1194x; 1.1015x over previous
#include <cuda_runtime.h>
#include <math.h>

#define Bb 64
#define Ll 128
#define Hh 128
#define Dd 16
#define NTOT (Bb*Ll*Ll)        // 1048576

typedef unsigned long long u64;

// ---------------- scratch ----------------
__device__ float g_Wt[Hh*Dd*Hh];            // [k][d*128+n]   1 MB
__device__ float g_Wrt[Dd*Hh];              // [d*128+n]
__device__ float g_encT[Bb*Hh*Ll];          // [b][k][j]      4 MB
__device__ float g_Q[(size_t)Bb*Dd*Hh*Ll];  // [b][d][n][j]   64 MB
__device__ float g_c[Bb*Ll*Dd];             // [b][j][d]
__device__ float g_LP[2u*NTOT];             // [dh][b][j][m]  8 MB

// ---------------- packed f32x2 helpers ----------------
__device__ __forceinline__ u64 ffma2(u64 a, u64 b, u64 c) {
    u64 d; asm("fma.rn.f32x2 %0, %1, %2, %3;" : "=l"(d) : "l"(a), "l"(b), "l"(c));
    return d;
}
__device__ __forceinline__ u64 dup2(float v) {
    u64 d; asm("mov.b64 %0, {%1, %2};" : "=l"(d) : "f"(v), "f"(v));
    return d;
}
__device__ __forceinline__ float2 unpack2(u64 v) {
    float2 r; asm("mov.b64 {%0, %1}, %2;" : "=f"(r.x), "=f"(r.y) : "l"(v));
    return r;
}

// ---------------- cp.async helpers ----------------
__device__ __forceinline__ unsigned int s2u(const void* p) {
    return (unsigned int)__cvta_generic_to_shared(p);
}
__device__ __forceinline__ void cpa16(unsigned int s, const void* g) {
    asm volatile("cp.async.cg.shared.global [%0], [%1], 16;" :: "r"(s), "l"(g));
}
__device__ __forceinline__ void cpa_commit() {
    asm volatile("cp.async.commit_group;" ::: "memory");
}
template<int N> __device__ __forceinline__ void cpa_wait() {
    asm volatile("cp.async.wait_group %0;" :: "n"(N) : "memory");
}

// ---------------- JAX threefry2x32, partitionable, key=(0,1) --------------
__device__ __forceinline__ unsigned int rotl32(unsigned int v, int s) {
    return (v << s) | (v >> (32 - s));
}
__device__ __forceinline__ unsigned int threefry_bits(unsigned int i) {
    const unsigned int ks0 = 0u, ks1 = 1u, ks2 = 0x1BD11BDAu ^ 0u ^ 1u;
    unsigned int x0 = 0u + ks0;
    unsigned int x1 = i + ks1;
#define TFR(r) { x0 += x1; x1 = rotl32(x1, r) ^ x0; }
    TFR(13) TFR(15) TFR(26) TFR(6)   x0 += ks1; x1 += ks2 + 1u;
    TFR(17) TFR(29) TFR(16) TFR(24)  x0 += ks2; x1 += ks0 + 2u;
    TFR(13) TFR(15) TFR(26) TFR(6)   x0 += ks0; x1 += ks1 + 3u;
    TFR(17) TFR(29) TFR(16) TFR(24)  x0 += ks1; x1 += ks2 + 4u;
    TFR(13) TFR(15) TFR(26) TFR(6)   x0 += ks2; x1 += ks0 + 5u;
#undef TFR
    return x0 ^ x1;
}

__device__ __forceinline__ float tanh_fast(float x) {
    float e = __expf(2.0f * x);
    return 1.0f - __fdividef(2.0f, e + 1.0f);
}

// ---------------- fused prep: coalesced W transpose, encT, linear ---------
__global__ void k_prep(const float* __restrict__ enc, const float* __restrict__ W,
                       const float* __restrict__ Wr, const float* __restrict__ Wl,
                       const float* __restrict__ Bvec) {
    __shared__ float t[32][33];
    int blk = blockIdx.x;
    int tid = threadIdx.x;
    if (blk < 1024) {
        // coalesced read of W; scattered (non-stalling) store to Wt
        int s = blk * 256 + tid;           // source idx, covers 262144
        int k = s >> 11;                   // s = (k*128 + n)*16 + d
        int n = (s >> 4) & 127;
        int d = s & 15;
        g_Wt[k * 2048 + d * 128 + n] = W[s];
        if (s < Dd * Hh) {                 // Wr[n,d] coalesced read
            int nn = s >> 4, dd = s & 15;
            g_Wrt[dd * 128 + nn] = Wr[s];
        }
    } else if (blk < 2048) {
        // enc[b][j][k] -> encT[b][k][j], 32x32 tiles
        int bb = blk - 1024;
        int b = bb >> 4;
        int rem = bb & 15;
        int j0 = (rem & 3) * 32, k0 = (rem >> 2) * 32;
        int tx = tid & 31, ty = tid >> 5;
#pragma unroll
        for (int i = 0; i < 32; i += 8)
            t[ty + i][tx] = enc[b * 16384 + (j0 + ty + i) * 128 + k0 + tx];
        __syncthreads();
#pragma unroll
        for (int i = 0; i < 32; i += 8)
            g_encT[b * 16384 + (k0 + ty + i) * 128 + j0 + tx] = t[tx][ty + i];
    } else {
        // c[b,j,d] = enc[b,j,:].Wl[:,d] + Bvec[d]
        int idx = (blk - 2048) * 256 + tid;
        int d = idx & 15;
        int bj = idx >> 4;
        const float* e = enc + (size_t)bj * Hh;
        float acc = Bvec[d];
#pragma unroll 8
        for (int k = 0; k < Hh; k++) acc = fmaf(e[k], Wl[k * Dd + d], acc);
        g_c[idx] = acc;
    }
}

#define ROWOP8(r, aval) { u64 a_ = dup2(aval); \
    acc[r][0] = ffma2(a_, b01.x, acc[r][0]); \
    acc[r][1] = ffma2(a_, b01.y, acc[r][1]); \
    acc[r][2] = ffma2(a_, b23.x, acc[r][2]); \
    acc[r][3] = ffma2(a_, b23.y, acc[r][3]); }

// ---------------- kernel 1 (R9 proven): Q[b][d][n][j] = (enc_b@Wt_d)^T+Wrt
// grid (16 d, 64 b), block 256, tile 128j x 128n, 8x8/thread,
// cp.async double-buffered sA chunks of 32 k
extern __shared__ char smemG[];
__global__ __launch_bounds__(256, 2) void k_gemm1() {
    float* sB  = (float*)smemG;                    // [128 k][128 n] 64 KB
    float* sA0 = (float*)(smemG + 65536);          // [32 k][128 j] 16 KB
    float* sA1 = (float*)(smemG + 65536 + 16384);  // [32 k][128 j] 16 KB
    int d = blockIdx.x, b = blockIdx.y;
    int tid = threadIdx.x;
    int tx = tid & 15, ty = tid >> 4;

    const float4* wsrc = (const float4*)g_Wt;
    const float4* asrc = (const float4*)(g_encT + (size_t)b * 16384);

    {
        unsigned int sBa = s2u(sB);
        for (int idx = tid; idx < 4096; idx += 256) {
            int k = idx >> 5, g = idx & 31;
            cpa16(sBa + (unsigned)(k * 32 + g) * 16, wsrc + (size_t)k * 512 + d * 32 + g);
        }
        unsigned int a0 = s2u(sA0);
        for (int idx = tid; idx < 1024; idx += 256)
            cpa16(a0 + (unsigned)idx * 16, asrc + idx);
        cpa_commit();
        unsigned int a1 = s2u(sA1);
        for (int idx = tid; idx < 1024; idx += 256)
            cpa16(a1 + (unsigned)idx * 16, asrc + 1024 + idx);
        cpa_commit();
    }
    cpa_wait<1>();
    __syncthreads();

    u64 acc[8][4];
#pragma unroll
    for (int r = 0; r < 8; r++)
#pragma unroll
        for (int q = 0; q < 4; q++) acc[r][q] = 0ull;

    for (int kc = 0; kc < 4; kc++) {
        float* sAc = (kc & 1) ? sA1 : sA0;
        int k0 = kc * 32;
        float4 a01_nx = *(const float4*)&sAc[ty * 8];
        float4 a23_nx = *(const float4*)&sAc[ty * 8 + 4];
        ulonglong2 b01_nx = *(const ulonglong2*)&sB[k0 * 128 + tx * 4];
        ulonglong2 b23_nx = *(const ulonglong2*)&sB[k0 * 128 + 64 + tx * 4];
#pragma unroll 4
        for (int kk = 0; kk < 32; kk++) {
            float4 a01 = a01_nx, a23 = a23_nx;
            ulonglong2 b01 = b01_nx, b23 = b23_nx;
            int kn = kk + 1;   // kk=31: stray reads into adjacent allocated smem
            a01_nx = *(const float4*)&sAc[kn * 128 + ty * 8];
            a23_nx = *(const float4*)&sAc[kn * 128 + ty * 8 + 4];
            b01_nx = *(const ulonglong2*)&sB[(k0 + kn) * 128 + tx * 4];
            b23_nx = *(const ulonglong2*)&sB[(k0 + kn) * 128 + 64 + tx * 4];
            ROWOP8(0, a01.x) ROWOP8(1, a01.y) ROWOP8(2, a01.z) ROWOP8(3, a01.w)
            ROWOP8(4, a23.x) ROWOP8(5, a23.y) ROWOP8(6, a23.z) ROWOP8(7, a23.w)
        }
        __syncthreads();
        if (kc + 2 < 4) {
            unsigned int aa = s2u(sAc);
            for (int idx = tid; idx < 1024; idx += 256)
                cpa16(aa + (unsigned)idx * 16, asrc + (kc + 2) * 1024 + idx);
            cpa_commit();
            cpa_wait<1>();
        } else {
            cpa_wait<0>();
        }
        __syncthreads();
    }

#pragma unroll
    for (int q = 0; q < 4; q++) {
        int colbase = (q < 2) ? (tx * 4 + 2 * q) : (64 + tx * 4 + 2 * (q - 2));
#pragma unroll
        for (int h = 0; h < 2; h++) {
            int col = colbase + h;
            float wr = g_Wrt[d * 128 + col];
            float v[8];
#pragma unroll
            for (int r = 0; r < 8; r++) {
                float2 s = unpack2(acc[r][q]);
                v[r] = (h == 0 ? s.x : s.y) + wr;
            }
            float* dst = g_Q + ((size_t)(b * 16 + d) * 128 + col) * 128 + ty * 8;
            *(float4*)dst       = make_float4(v[0], v[1], v[2], v[3]);
            *(float4*)(dst + 4) = make_float4(v[4], v[5], v[6], v[7]);
        }
    }
}

// ---------------- kernel 2: bilinear + tanh + partial logits --------------
// grid (2 mh, 2 dh, 64 b) = 256 CTAs. Tile 128j x 64m, 8 d (16 n-half phases).
// j-paired FFMA2: A = 4 natural j-pair u64 (2 LDS.128), E = 4 m scalars
// (1 LDS.128, dup'd). 16 FFMA2 / ~23 issues per n.
extern __shared__ char smemF[];
__global__ __launch_bounds__(256, 2) void k_final(const float* __restrict__ U) {
    float* sQ0 = (float*)smemF;                    // [64 n][128 j] 32 KB
    float* sQ1 = (float*)(smemF + 32768);          // [64 n][128 j] 32 KB
    float* sE  = (float*)(smemF + 65536);          // [128 n][64 m] 32 KB
    float* sC  = (float*)(smemF + 98304);          // [128 j][16 d] 8 KB
    float* sU  = sC + 2048;
    int mh = blockIdx.x, dh = blockIdx.y, b = blockIdx.z;
    int tid = threadIdx.x;
    int tx = tid & 15, ty = tid >> 4;              // m cols tx*4, j rows ty*8 (4 pairs)
    int w = tid >> 5, l = tid & 31;

    const float4* qsrc = (const float4*)g_Q;

    // warp-partitioned refill of a 64-n half of Q_d (warp w owns j [w*16,+16))
    auto refillQ = [&](float* buf, int p) {
        int d = dh * 8 + (p >> 1), hh = p & 1;
        const float4* src = qsrc + (size_t)(b * 16 + d) * 4096 + hh * 2048;
        unsigned int dst = s2u(buf);
#pragma unroll
        for (int t = 0; t < 8; t++) {
            int nn = t * 8 + (l >> 2);
            int gg = w * 4 + (l & 3);
            cpa16(dst + (unsigned)(nn * 32 + gg) * 16, src + nn * 32 + gg);
        }
    };

    // prologue
    {
        const float4* esrc = (const float4*)(g_encT + (size_t)b * 16384);
        unsigned int ea = s2u(sE);
        for (int idx = tid; idx < 2048; idx += 256) {
            int n = idx >> 4, gg = idx & 15;
            cpa16(ea + (unsigned)idx * 16, esrc + n * 32 + mh * 16 + gg);
        }
        refillQ(sQ0, 0);
        cpa_commit();
        refillQ(sQ1, 1);
        cpa_commit();
        const float4* csrc = (const float4*)(g_c + b * 2048);
        float4* cdst = (float4*)sC;
        for (int idx = tid; idx < 512; idx += 256) cdst[idx] = csrc[idx];
        if (tid < 16) sU[tid] = U[tid];
    }
    cpa_wait<1>();
    __syncthreads();   // sE/sC cross-warp + phase0 visible

    float logit[8][4];                 // [j-local][m-local]
#pragma unroll
    for (int r = 0; r < 8; r++)
#pragma unroll
        for (int q = 0; q < 4; q++) logit[r][q] = 0.0f;

    u64 acc[4][4];                     // [j-pair q][m mi]

    for (int p = 0; p < 16; p++) {
        int d = dh * 8 + (p >> 1), hh = p & 1;
        float* sQc = hh ? sQ1 : sQ0;
        if (hh == 0) {
#pragma unroll
            for (int q = 0; q < 4; q++)
#pragma unroll
                for (int mi = 0; mi < 4; mi++) acc[q][mi] = 0ull;
        }
        {
            ulonglong2 a01_nx = *(const ulonglong2*)&sQc[ty * 8];
            ulonglong2 a23_nx = *(const ulonglong2*)&sQc[ty * 8 + 4];
            float4 e_nx = *(const float4*)&sE[(hh * 64) * 64 + tx * 4];
#pragma unroll 4
            for (int nn = 0; nn < 64; nn++) {
                ulonglong2 a01 = a01_nx, a23 = a23_nx;
                float4 ee = e_nx;
                int kn = nn + 1;   // nn=63: stray reads into adjacent allocated smem
                a01_nx = *(const ulonglong2*)&sQc[kn * 128 + ty * 8];
                a23_nx = *(const ulonglong2*)&sQc[kn * 128 + ty * 8 + 4];
                e_nx   = *(const float4*)&sE[(hh * 64 + kn) * 64 + tx * 4];
                u64 e0 = dup2(ee.x), e1 = dup2(ee.y), e2 = dup2(ee.z), e3 = dup2(ee.w);
                acc[0][0] = ffma2(a01.x, e0, acc[0][0]);
                acc[1][0] = ffma2(a01.y, e0, acc[1][0]);
                acc[2][0] = ffma2(a23.x, e0, acc[2][0]);
                acc[3][0] = ffma2(a23.y, e0, acc[3][0]);
                acc[0][1] = ffma2(a01.x, e1, acc[0][1]);
                acc[1][1] = ffma2(a01.y, e1, acc[1][1]);
                acc[2][1] = ffma2(a23.x, e1, acc[2][1]);
                acc[3][1] = ffma2(a23.y, e1, acc[3][1]);
                acc[0][2] = ffma2(a01.x, e2, acc[0][2]);
                acc[1][2] = ffma2(a01.y, e2, acc[1][2]);
                acc[2][2] = ffma2(a23.x, e2, acc[2][2]);
                acc[3][2] = ffma2(a23.y, e2, acc[3][2]);
                acc[0][3] = ffma2(a01.x, e3, acc[0][3]);
                acc[1][3] = ffma2(a01.y, e3, acc[1][3]);
                acc[2][3] = ffma2(a23.x, e3, acc[2][3]);
                acc[3][3] = ffma2(a23.y, e3, acc[3][3]);
            }
        }
        if (hh == 1) {
            float ud = sU[d];
#pragma unroll
            for (int q = 0; q < 4; q++) {
                float c0 = sC[(ty * 8 + 2 * q) * 16 + d];
                float c1 = sC[(ty * 8 + 2 * q + 1) * 16 + d];
#pragma unroll
                for (int mi = 0; mi < 4; mi++) {
                    float2 s = unpack2(acc[q][mi]);
                    logit[2 * q][mi]     = fmaf(ud, tanh_fast(s.x + c0), logit[2 * q][mi]);
                    logit[2 * q + 1][mi] = fmaf(ud, tanh_fast(s.y + c1), logit[2 * q + 1][mi]);
                }
            }
        }
        if (p <= 13) {
            refillQ(sQc, p + 2);
            cpa_commit();
            cpa_wait<1>();
        } else {
            cpa_wait<0>();
        }
        __syncwarp();
    }

    // write partial logits
#pragma unroll
    for (int r = 0; r < 8; r++) {
        int j = ty * 8 + r;
        size_t o = (size_t)dh * NTOT + (size_t)b * 16384 + (size_t)j * 128 + mh * 64 + tx * 4;
        *(float4*)(g_LP + o) = make_float4(logit[r][0], logit[r][1], logit[r][2], logit[r][3]);
    }
}

// ---------------- kernel E: combine + mask/sigmoid/RNG/entropy ------------
__global__ __launch_bounds__(256) void k_epi(const float* __restrict__ lb,
                                             float* __restrict__ out) {
    int gid = blockIdx.x * blockDim.x + threadIdx.x;
    const float4* P0 = (const float4*)g_LP;
    const float4* P1 = P0 + (NTOT / 4);
    float4 a = P0[gid], c = P1[gid];
    float lbias = lb[0];
    float s4[4] = { a.x + c.x + lbias, a.y + c.y + lbias,
                    a.z + c.z + lbias, a.w + c.w + lbias };
    int flat0 = gid * 4;
    int j = (flat0 >> 7) & 127;
    int m0 = flat0 & 127;
    float vs[4], ve[4];
#pragma unroll
    for (int e = 0; e < 4; e++) {
        float s = s4[e];
        if (j == m0 + e) s -= 1e8f;
        s4[e] = s;
        float p = 1.0f / (1.0f + expf(-s));
        unsigned int bits = threefry_bits((unsigned int)(flat0 + e));
        float u = __uint_as_float((bits >> 9) | 0x3f800000u) - 1.0f;
        vs[e] = (u < p) ? 1.0f : 0.0f;
        float ax = fabsf(s);
        float lse = log1pf(expf(-ax));
        float spp = fmaxf(s, 0.0f) + lse;
        float spn = fmaxf(-s, 0.0f) + lse;
        ve[e] = p * spn + (1.0f - p) * spp;
    }
    ((float4*)out)[gid]                = make_float4(vs[0], vs[1], vs[2], vs[3]);
    ((float4*)(out + NTOT))[gid]       = make_float4(s4[0], s4[1], s4[2], s4[3]);
    ((float4*)(out + 2u * NTOT))[gid]  = make_float4(ve[0], ve[1], ve[2], ve[3]);
}

// ---------------- launch ----------------
extern "C" void kernel_launch(void* const* d_in, const int* in_sizes, int n_in,
                              void* d_out, int out_size) {
    const float* enc  = (const float*)d_in[0];
    const float* W    = (const float*)d_in[1];
    const float* Wl   = (const float*)d_in[2];
    const float* Wr   = (const float*)d_in[3];
    const float* U    = (const float*)d_in[4];
    const float* Bv   = (const float*)d_in[5];
    const float* lbias= (const float*)d_in[6];
    float* out = (float*)d_out;

    k_prep<<<1024 + 1024 + 512, 256>>>(enc, W, Wr, Wl, Bv);

    int smemG_bytes = 65536 + 16384 * 2 + 1024;
    cudaFuncSetAttribute(k_gemm1, cudaFuncAttributeMaxDynamicSharedMemorySize, smemG_bytes);
    k_gemm1<<<dim3(16, Bb), 256, smemG_bytes>>>();

    int smemF_bytes = 32768 * 2 + 32768 + 8192 + 64 + 512;
    cudaFuncSetAttribute(k_final, cudaFuncAttributeMaxDynamicSharedMemorySize, smemF_bytes);
    k_final<<<dim3(2, 2, Bb), 256, smemF_bytes>>>(U);

    k_epi<<<NTOT / 4 / 256, 256>>>(lbias, out);
}

// round 15
// speedup vs baseline: 1.1394x; 1.0178x over previous
#include <cuda_runtime.h>
#include <math.h>

#define Bb 64
#define Ll 128
#define Hh 128
#define Dd 16
#define NTOT (Bb*Ll*Ll)        // 1048576

typedef unsigned long long u64;

// ---------------- scratch ----------------
__device__ float g_Wt[Hh*Dd*Hh];            // [k][d*128+n]   1 MB
__device__ float g_Wrt[Dd*Hh];              // [d*128+n]
__device__ float g_encT[Bb*Hh*Ll];          // [b][k][j]      4 MB
__device__ float g_Q[(size_t)Bb*Dd*Hh*Ll];  // [b][d][n][j]   64 MB
__device__ float g_c[Bb*Ll*Dd];             // [b][j][d]
__device__ float g_LP[2u*NTOT];             // [dh][b][j][m]  8 MB

// ---------------- packed f32x2 helpers ----------------
__device__ __forceinline__ u64 ffma2(u64 a, u64 b, u64 c) {
    u64 d; asm("fma.rn.f32x2 %0, %1, %2, %3;" : "=l"(d) : "l"(a), "l"(b), "l"(c));
    return d;
}
__device__ __forceinline__ u64 dup2(float v) {
    u64 d; asm("mov.b64 %0, {%1, %2};" : "=l"(d) : "f"(v), "f"(v));
    return d;
}
__device__ __forceinline__ float2 unpack2(u64 v) {
    float2 r; asm("mov.b64 {%0, %1}, %2;" : "=f"(r.x), "=f"(r.y) : "l"(v));
    return r;
}

// ---------------- cp.async helpers ----------------
__device__ __forceinline__ unsigned int s2u(const void* p) {
    return (unsigned int)__cvta_generic_to_shared(p);
}
__device__ __forceinline__ void cpa16(unsigned int s, const void* g) {
    asm volatile("cp.async.cg.shared.global [%0], [%1], 16;" :: "r"(s), "l"(g));
}
__device__ __forceinline__ void cpa_commit() {
    asm volatile("cp.async.commit_group;" ::: "memory");
}
template<int N> __device__ __forceinline__ void cpa_wait() {
    asm volatile("cp.async.wait_group %0;" :: "n"(N) : "memory");
}

// ---------------- JAX threefry2x32, partitionable, key=(0,1) --------------
__device__ __forceinline__ unsigned int rotl32(unsigned int v, int s) {
    return (v << s) | (v >> (32 - s));
}
__device__ __forceinline__ unsigned int threefry_bits(unsigned int i) {
    const unsigned int ks0 = 0u, ks1 = 1u, ks2 = 0x1BD11BDAu ^ 0u ^ 1u;
    unsigned int x0 = 0u + ks0;
    unsigned int x1 = i + ks1;
#define TFR(r) { x0 += x1; x1 = rotl32(x1, r) ^ x0; }
    TFR(13) TFR(15) TFR(26) TFR(6)   x0 += ks1; x1 += ks2 + 1u;
    TFR(17) TFR(29) TFR(16) TFR(24)  x0 += ks2; x1 += ks0 + 2u;
    TFR(13) TFR(15) TFR(26) TFR(6)   x0 += ks0; x1 += ks1 + 3u;
    TFR(17) TFR(29) TFR(16) TFR(24)  x0 += ks1; x1 += ks2 + 4u;
    TFR(13) TFR(15) TFR(26) TFR(6)   x0 += ks2; x1 += ks0 + 5u;
#undef TFR
    return x0 ^ x1;
}

__device__ __forceinline__ float tanh_fast(float x) {
    float e = __expf(2.0f * x);
    return 1.0f - __fdividef(2.0f, e + 1.0f);
}

// ---------------- fused prep: float4 W transpose, encT, linear ------------
__global__ void k_prep(const float* __restrict__ enc, const float* __restrict__ W,
                       const float* __restrict__ Wr, const float* __restrict__ Wl,
                       const float* __restrict__ Bvec) {
    __shared__ float t[32][33];
    int blk = blockIdx.x;
    int tid = threadIdx.x;
    if (blk < 256) {
        // W: one float4 = 4 consecutive d at fixed (k,n); scattered stores
        int s4 = blk * 256 + tid;              // 0..65535 float4 over W
        float4 v = ((const float4*)W)[s4];
        int lin = s4 * 4;                      // = (k*128+n)*16 + d0
        int k = lin >> 11;
        int n = (lin >> 4) & 127;
        int d0 = lin & 15;                     // 0,4,8,12
        g_Wt[k * 2048 + (d0 + 0) * 128 + n] = v.x;
        g_Wt[k * 2048 + (d0 + 1) * 128 + n] = v.y;
        g_Wt[k * 2048 + (d0 + 2) * 128 + n] = v.z;
        g_Wt[k * 2048 + (d0 + 3) * 128 + n] = v.w;
        if (s4 < 512) {                        // Wr[n,d]: 2048 floats
            float4 w = ((const float4*)Wr)[s4];
            int lin2 = s4 * 4;
            int nn = lin2 >> 4, dd = lin2 & 15;
            g_Wrt[(dd + 0) * 128 + nn] = w.x;
            g_Wrt[(dd + 1) * 128 + nn] = w.y;
            g_Wrt[(dd + 2) * 128 + nn] = w.z;
            g_Wrt[(dd + 3) * 128 + nn] = w.w;
        }
    } else if (blk < 256 + 1024) {
        // enc[b][j][k] -> encT[b][k][j], 32x32 tiles
        int bb = blk - 256;
        int b = bb >> 4;
        int rem = bb & 15;
        int j0 = (rem & 3) * 32, k0 = (rem >> 2) * 32;
        int tx = tid & 31, ty = tid >> 5;
#pragma unroll
        for (int i = 0; i < 32; i += 8)
            t[ty + i][tx] = enc[b * 16384 + (j0 + ty + i) * 128 + k0 + tx];
        __syncthreads();
#pragma unroll
        for (int i = 0; i < 32; i += 8)
            g_encT[b * 16384 + (k0 + ty + i) * 128 + j0 + tx] = t[tx][ty + i];
    } else {
        // c[b,j,d] = enc[b,j,:].Wl[:,d] + Bvec[d]
        int idx = (blk - 1280) * 256 + tid;
        int d = idx & 15;
        int bj = idx >> 4;
        const float* e = enc + (size_t)bj * Hh;
        float acc = Bvec[d];
#pragma unroll 8
        for (int k = 0; k < Hh; k++) acc = fmaf(e[k], Wl[k * Dd + d], acc);
        g_c[idx] = acc;
    }
}

#define ROWOP8(r, aval) { u64 a_ = dup2(aval); \
    acc[r][0] = ffma2(a_, b01.x, acc[r][0]); \
    acc[r][1] = ffma2(a_, b01.y, acc[r][1]); \
    acc[r][2] = ffma2(a_, b23.x, acc[r][2]); \
    acc[r][3] = ffma2(a_, b23.y, acc[r][3]); }

// ---------------- kernel 1 (R9 proven): Q[b][d][n][j] = (enc_b@Wt_d)^T+Wrt
// grid (16 d, 64 b), block 256, tile 128j x 128n, 8x8/thread,
// cp.async double-buffered sA chunks of 32 k
extern __shared__ char smemG[];
__global__ __launch_bounds__(256, 2) void k_gemm1() {
    float* sB  = (float*)smemG;                    // [128 k][128 n] 64 KB
    float* sA0 = (float*)(smemG + 65536);          // [32 k][128 j] 16 KB
    float* sA1 = (float*)(smemG + 65536 + 16384);  // [32 k][128 j] 16 KB
    int d = blockIdx.x, b = blockIdx.y;
    int tid = threadIdx.x;
    int tx = tid & 15, ty = tid >> 4;

    const float4* wsrc = (const float4*)g_Wt;
    const float4* asrc = (const float4*)(g_encT + (size_t)b * 16384);

    {
        unsigned int sBa = s2u(sB);
        for (int idx = tid; idx < 4096; idx += 256) {
            int k = idx >> 5, g = idx & 31;
            cpa16(sBa + (unsigned)(k * 32 + g) * 16, wsrc + (size_t)k * 512 + d * 32 + g);
        }
        unsigned int a0 = s2u(sA0);
        for (int idx = tid; idx < 1024; idx += 256)
            cpa16(a0 + (unsigned)idx * 16, asrc + idx);
        cpa_commit();
        unsigned int a1 = s2u(sA1);
        for (int idx = tid; idx < 1024; idx += 256)
            cpa16(a1 + (unsigned)idx * 16, asrc + 1024 + idx);
        cpa_commit();
    }
    cpa_wait<1>();
    __syncthreads();

    u64 acc[8][4];
#pragma unroll
    for (int r = 0; r < 8; r++)
#pragma unroll
        for (int q = 0; q < 4; q++) acc[r][q] = 0ull;

    for (int kc = 0; kc < 4; kc++) {
        float* sAc = (kc & 1) ? sA1 : sA0;
        int k0 = kc * 32;
        float4 a01_nx = *(const float4*)&sAc[ty * 8];
        float4 a23_nx = *(const float4*)&sAc[ty * 8 + 4];
        ulonglong2 b01_nx = *(const ulonglong2*)&sB[k0 * 128 + tx * 4];
        ulonglong2 b23_nx = *(const ulonglong2*)&sB[k0 * 128 + 64 + tx * 4];
#pragma unroll 8
        for (int kk = 0; kk < 32; kk++) {
            float4 a01 = a01_nx, a23 = a23_nx;
            ulonglong2 b01 = b01_nx, b23 = b23_nx;
            int kn = kk + 1;   // kk=31: stray reads into adjacent allocated smem
            a01_nx = *(const float4*)&sAc[kn * 128 + ty * 8];
            a23_nx = *(const float4*)&sAc[kn * 128 + ty * 8 + 4];
            b01_nx = *(const ulonglong2*)&sB[(k0 + kn) * 128 + tx * 4];
            b23_nx = *(const ulonglong2*)&sB[(k0 + kn) * 128 + 64 + tx * 4];
            ROWOP8(0, a01.x) ROWOP8(1, a01.y) ROWOP8(2, a01.z) ROWOP8(3, a01.w)
            ROWOP8(4, a23.x) ROWOP8(5, a23.y) ROWOP8(6, a23.z) ROWOP8(7, a23.w)
        }
        __syncthreads();
        if (kc + 2 < 4) {
            unsigned int aa = s2u(sAc);
            for (int idx = tid; idx < 1024; idx += 256)
                cpa16(aa + (unsigned)idx * 16, asrc + (kc + 2) * 1024 + idx);
            cpa_commit();
            cpa_wait<1>();
        } else {
            cpa_wait<0>();
        }
        __syncthreads();
    }

#pragma unroll
    for (int q = 0; q < 4; q++) {
        int colbase = (q < 2) ? (tx * 4 + 2 * q) : (64 + tx * 4 + 2 * (q - 2));
#pragma unroll
        for (int h = 0; h < 2; h++) {
            int col = colbase + h;
            float wr = g_Wrt[d * 128 + col];
            float v[8];
#pragma unroll
            for (int r = 0; r < 8; r++) {
                float2 s = unpack2(acc[r][q]);
                v[r] = (h == 0 ? s.x : s.y) + wr;
            }
            float* dst = g_Q + ((size_t)(b * 16 + d) * 128 + col) * 128 + ty * 8;
            *(float4*)dst       = make_float4(v[0], v[1], v[2], v[3]);
            *(float4*)(dst + 4) = make_float4(v[4], v[5], v[6], v[7]);
        }
    }
}

// ---------------- kernel 2: bilinear + tanh + partial logits --------------
// grid (2 mh, 2 dh, 64 b) = 256 CTAs. Tile 128j x 64m, 8 d (16 n-half phases).
// j-paired FFMA2. lbias folded into dh==0 logit init.
extern __shared__ char smemF[];
__global__ __launch_bounds__(256, 2) void k_final(const float* __restrict__ U,
                                                  const float* __restrict__ lb) {
    float* sQ0 = (float*)smemF;                    // [64 n][128 j] 32 KB
    float* sQ1 = (float*)(smemF + 32768);          // [64 n][128 j] 32 KB
    float* sE  = (float*)(smemF + 65536);          // [128 n][64 m] 32 KB
    float* sC  = (float*)(smemF + 98304);          // [128 j][16 d] 8 KB
    float* sU  = sC + 2048;
    int mh = blockIdx.x, dh = blockIdx.y, b = blockIdx.z;
    int tid = threadIdx.x;
    int tx = tid & 15, ty = tid >> 4;              // m cols tx*4, j rows ty*8 (4 pairs)
    int w = tid >> 5, l = tid & 31;

    const float4* qsrc = (const float4*)g_Q;

    auto refillQ = [&](float* buf, int p) {
        int d = dh * 8 + (p >> 1), hh = p & 1;
        const float4* src = qsrc + (size_t)(b * 16 + d) * 4096 + hh * 2048;
        unsigned int dst = s2u(buf);
#pragma unroll
        for (int t = 0; t < 8; t++) {
            int nn = t * 8 + (l >> 2);
            int gg = w * 4 + (l & 3);
            cpa16(dst + (unsigned)(nn * 32 + gg) * 16, src + nn * 32 + gg);
        }
    };

    {
        const float4* esrc = (const float4*)(g_encT + (size_t)b * 16384);
        unsigned int ea = s2u(sE);
        for (int idx = tid; idx < 2048; idx += 256) {
            int n = idx >> 4, gg = idx & 15;
            cpa16(ea + (unsigned)idx * 16, esrc + n * 32 + mh * 16 + gg);
        }
        refillQ(sQ0, 0);
        cpa_commit();
        refillQ(sQ1, 1);
        cpa_commit();
        const float4* csrc = (const float4*)(g_c + b * 2048);
        float4* cdst = (float4*)sC;
        for (int idx = tid; idx < 512; idx += 256) cdst[idx] = csrc[idx];
        if (tid < 16) sU[tid] = U[tid];
    }
    cpa_wait<1>();
    __syncthreads();

    float init = (dh == 0) ? lb[0] : 0.0f;
    float logit[8][4];                 // [j-local][m-local]
#pragma unroll
    for (int r = 0; r < 8; r++)
#pragma unroll
        for (int q = 0; q < 4; q++) logit[r][q] = init;

    u64 acc[4][4];                     // [j-pair q][m mi]

    for (int p = 0; p < 16; p++) {
        int d = dh * 8 + (p >> 1), hh = p & 1;
        float* sQc = hh ? sQ1 : sQ0;
        if (hh == 0) {
#pragma unroll
            for (int q = 0; q < 4; q++)
#pragma unroll
                for (int mi = 0; mi < 4; mi++) acc[q][mi] = 0ull;
        }
        {
            ulonglong2 a01_nx = *(const ulonglong2*)&sQc[ty * 8];
            ulonglong2 a23_nx = *(const ulonglong2*)&sQc[ty * 8 + 4];
            float4 e_nx = *(const float4*)&sE[(hh * 64) * 64 + tx * 4];
#pragma unroll 8
            for (int nn = 0; nn < 64; nn++) {
                ulonglong2 a01 = a01_nx, a23 = a23_nx;
                float4 ee = e_nx;
                int kn = nn + 1;   // nn=63: stray reads into adjacent allocated smem
                a01_nx = *(const ulonglong2*)&sQc[kn * 128 + ty * 8];
                a23_nx = *(const ulonglong2*)&sQc[kn * 128 + ty * 8 + 4];
                e_nx   = *(const float4*)&sE[(hh * 64 + kn) * 64 + tx * 4];
                u64 e0 = dup2(ee.x), e1 = dup2(ee.y), e2 = dup2(ee.z), e3 = dup2(ee.w);
                acc[0][0] = ffma2(a01.x, e0, acc[0][0]);
                acc[1][0] = ffma2(a01.y, e0, acc[1][0]);
                acc[2][0] = ffma2(a23.x, e0, acc[2][0]);
                acc[3][0] = ffma2(a23.y, e0, acc[3][0]);
                acc[0][1] = ffma2(a01.x, e1, acc[0][1]);
                acc[1][1] = ffma2(a01.y, e1, acc[1][1]);
                acc[2][1] = ffma2(a23.x, e1, acc[2][1]);
                acc[3][1] = ffma2(a23.y, e1, acc[3][1]);
                acc[0][2] = ffma2(a01.x, e2, acc[0][2]);
                acc[1][2] = ffma2(a01.y, e2, acc[1][2]);
                acc[2][2] = ffma2(a23.x, e2, acc[2][2]);
                acc[3][2] = ffma2(a23.y, e2, acc[3][2]);
                acc[0][3] = ffma2(a01.x, e3, acc[0][3]);
                acc[1][3] = ffma2(a01.y, e3, acc[1][3]);
                acc[2][3] = ffma2(a23.x, e3, acc[2][3]);
                acc[3][3] = ffma2(a23.y, e3, acc[3][3]);
            }
        }
        if (hh == 1) {
            float ud = sU[d];
#pragma unroll
            for (int q = 0; q < 4; q++) {
                float c0 = sC[(ty * 8 + 2 * q) * 16 + d];
                float c1 = sC[(ty * 8 + 2 * q + 1) * 16 + d];
#pragma unroll
                for (int mi = 0; mi < 4; mi++) {
                    float2 s = unpack2(acc[q][mi]);
                    logit[2 * q][mi]     = fmaf(ud, tanh_fast(s.x + c0), logit[2 * q][mi]);
                    logit[2 * q + 1][mi] = fmaf(ud, tanh_fast(s.y + c1), logit[2 * q + 1][mi]);
                }
            }
        }
        if (p <= 13) {
            refillQ(sQc, p + 2);
            cpa_commit();
            cpa_wait<1>();
        } else {
            cpa_wait<0>();
        }
        __syncwarp();
    }

    // write partial logits
#pragma unroll
    for (int r = 0; r < 8; r++) {
        int j = ty * 8 + r;
        size_t o = (size_t)dh * NTOT + (size_t)b * 16384 + (size_t)j * 128 + mh * 64 + tx * 4;
        *(float4*)(g_LP + o) = make_float4(logit[r][0], logit[r][1], logit[r][2], logit[r][3]);
    }
}

// ---------------- kernel E: combine + mask/sigmoid/RNG/entropy ------------
__global__ __launch_bounds__(256) void k_epi(float* __restrict__ out) {
    int gid = blockIdx.x * blockDim.x + threadIdx.x;
    const float4* P0 = (const float4*)g_LP;
    const float4* P1 = P0 + (NTOT / 4);
    float4 a = P0[gid], c = P1[gid];
    float s4[4] = { a.x + c.x, a.y + c.y, a.z + c.z, a.w + c.w };
    int flat0 = gid * 4;
    int j = (flat0 >> 7) & 127;
    int m0 = flat0 & 127;
    float vs[4], ve[4];
#pragma unroll
    for (int e = 0; e < 4; e++) {
        float s = s4[e];
        if (j == m0 + e) s -= 1e8f;
        s4[e] = s;
        float p = 1.0f / (1.0f + expf(-s));
        unsigned int bits = threefry_bits((unsigned int)(flat0 + e));
        float u = __uint_as_float((bits >> 9) | 0x3f800000u) - 1.0f;
        vs[e] = (u < p) ? 1.0f : 0.0f;
        float ax = fabsf(s);
        float lse = log1pf(expf(-ax));
        float spp = fmaxf(s, 0.0f) + lse;
        float spn = fmaxf(-s, 0.0f) + lse;
        ve[e] = p * spn + (1.0f - p) * spp;
    }
    ((float4*)out)[gid]                = make_float4(vs[0], vs[1], vs[2], vs[3]);
    ((float4*)(out + NTOT))[gid]       = make_float4(s4[0], s4[1], s4[2], s4[3]);
    ((float4*)(out + 2u * NTOT))[gid]  = make_float4(ve[0], ve[1], ve[2], ve[3]);
}

// ---------------- launch ----------------
extern "C" void kernel_launch(void* const* d_in, const int* in_sizes, int n_in,
                              void* d_out, int out_size) {
    const float* enc  = (const float*)d_in[0];
    const float* W    = (const float*)d_in[1];
    const float* Wl   = (const float*)d_in[2];
    const float* Wr   = (const float*)d_in[3];
    const float* U    = (const float*)d_in[4];
    const float* Bv   = (const float*)d_in[5];
    const float* lbias= (const float*)d_in[6];
    float* out = (float*)d_out;

    k_prep<<<256 + 1024 + 512, 256>>>(enc, W, Wr, Wl, Bv);

    int smemG_bytes = 65536 + 16384 * 2 + 1024;
    cudaFuncSetAttribute(k_gemm1, cudaFuncAttributeMaxDynamicSharedMemorySize, smemG_bytes);
    k_gemm1<<<dim3(16, Bb), 256, smemG_bytes>>>();

    int smemF_bytes = 32768 * 2 + 32768 + 8192 + 64 + 512;
    cudaFuncSetAttribute(k_final, cudaFuncAttributeMaxDynamicSharedMemorySize, smemF_bytes);
    k_final<<<dim3(2, 2, Bb), 256, smemF_bytes>>>(U, lbias);

    k_epi<<<NTOT / 4 / 256, 256>>>(out);
}